// round 14
// baseline (speedup 1.0000x reference)
#include <cuda_runtime.h>

// StateSpaceDiffusionModel reduced to scalar order-64 IIR+FIR (transposed
// direct form II, validated R1-R12):
//   y_t = c0*u_t + S_1(t)
//   S_i(t+1) = S_{i+1}(t) + A'_i*y_t + C'_i*u_t   (i=1..64, S_65=0)
// A'_i = a_{i-1}, C'_i = c_i (i<=63, else 0).
//
// R13: EIGHT-step symbolic fold. Exact identities (shift part exact because
// mixing enters only through row 1, whose S-support stays <= 8 over 8 steps):
//   S_i(t+8) = S_{i+8}(t) + sum_{j=1..8} Gam[i][j]*S_j(t) + sum_m Pi[i][m]*u_m
//   y_{t+m}  = sum_{j=1..8} E[m][j]*S_j(t) + sum_s F[m][s]*u_s
// Gam/Pi/E/F precomputed per head by fold_kernel (thread = one column of the
// evolving 64x(64+8) transfer matrix, kept in registers).
// Scan: warp = 4 seq x 8 lanes; lane r owns slots 8r+1..8r+8 (4 pairs).
// State lives in SMEM between iterations: one STS + one BAR + LDS per 8 steps.
// Cross-lane exchange happens ONCE per 8 steps (vs once per 2 steps before).

#define HH 512
#define NN 64
#define BB 16
#define LL 2048

typedef unsigned long long ull;

__device__ float g_a[HH * NN];
__device__ float g_c[HH * NN];
__device__ ull   g_TG [HH * 32 * 8];   // Gamma pairs: [h][pair pg][j0], slots (2pg+1,2pg+2)
__device__ ull   g_TPi[HH * 32 * 8];   // Pi pairs:    [h][pair pg][m]
__device__ float g_E[HH * 8 * 8];      // y solve:     [h][m][j0]
__device__ float g_F[HH * 8 * 8];      //              [h][m][s] (c0 on diag included)

// ---------------- packed f32x2 helpers ----------------
__device__ __forceinline__ ull pack2(float lo, float hi) {
    ull r; asm("mov.b64 %0, {%1,%2};" : "=l"(r) : "f"(lo), "f"(hi)); return r;
}
__device__ __forceinline__ void unpack2(ull v, float& lo, float& hi) {
    asm("mov.b64 {%0,%1}, %2;" : "=f"(lo), "=f"(hi) : "l"(v));
}
__device__ __forceinline__ ull fma2(ull a, ull b, ull c) {
    ull d; asm("fma.rn.f32x2 %0, %1, %2, %3;" : "=l"(d) : "l"(a), "l"(b), "l"(c)); return d;
}

// ---------------- Kernel 1: per-head base coefficients ----------------
__global__ void coef_kernel(const float* __restrict__ k) {
    __shared__ float sh[NN];
    __shared__ float shd[NN];
    __shared__ float shP[NN];
    __shared__ float shsum;
    int h = blockIdx.x;
    int j = threadIdx.x;
    float kv = k[h * NN + j];
    float kc = fminf(fmaxf(kv, 1.0f / 16.0f), 1.0f);
    sh[j] = kc;
    __syncthreads();
    if (j == 0) {
        float s = 0.f;
        for (int i = 0; i < NN; i++) s += sh[i];
        shsum = s;
    }
    __syncthreads();
    float kn = kc / shsum;                       // L1-normalized clamped k
    float s = (j < NN - 1) ? (1.0f + kn) : kn;   // column L1 norm of (A + b k^T)
    float w = kn / s;                            // M[0, j]
    shd[j] = 1.0f / s;                           // subdiagonal
    __syncthreads();
    if (j == 0) {
        float P = 1.f;
        for (int i = 0; i < NN; i++) { shP[i] = P; P *= shd[i]; }
    }
    __syncthreads();
    float Pj = shP[j];
    g_a[h * NN + j] = w * Pj;    // a_j  (A'_i = g_a[i-1])
    g_c[h * NN + j] = kv * Pj;   // c_j  (C'_i = g_c[i], i<=63; c0 = g_c[0])
}

// ---------------- Kernel 1b: symbolic 8-step fold ----------------
// Block per head, 96 threads (72 active). Thread c owns one column of the
// evolving transfer matrix: c in [0,64) -> S-column j=c+1 ; c in [64,72) ->
// u-column s=c-64. w[i] (i=1..64) kept in registers, w[65]=0 invariant.
// One step m: y = w[1] + c0*ind ; w[i] = w[i+1] + A'_i*y + C'_i*ind (asc).
__global__ void __launch_bounds__(96)
fold_kernel() {
    __shared__ float sA[NN];     // A'_i at sA[i-1]
    __shared__ float sC[NN + 1]; // C'_i at sC[i], sC[0]=c0, sC[64]=0
    int h = blockIdx.x;
    int c = threadIdx.x;
    if (c < NN) { sA[c] = g_a[h * NN + c]; sC[c] = g_c[h * NN + c]; }
    if (c == 64) sC[NN] = 0.f;
    __syncthreads();

    if (c < 72) {
        float w[66];  // w[1..64]; w[65] stays 0
#pragma unroll
        for (int i = 0; i <= 65; i++) w[i] = 0.f;
        if (c < 64) w[c + 1] = 1.f;   // S-column j=c+1 starts as identity

        float c0 = sC[0];
        float yv[8];
#pragma unroll
        for (int m = 0; m < 8; m++) {
            float ind = (c == 64 + m) ? 1.f : 0.f;
            float yy = fmaf(c0, ind, w[1]);
            yv[m] = yy;
#pragma unroll
            for (int i = 1; i <= 64; i++)           // ascending: w[i+1] still old
                w[i] = w[i + 1] + sA[i - 1] * yy + sC[i] * ind;
            // note sC[64]=0 handles C'_64
        }

        if (c < 8) {
            // Gamma column j0=c ; E[m][j0=c]
#pragma unroll
            for (int pg = 0; pg < 32; pg++)
                g_TG[(h * 32 + pg) * 8 + c] = pack2(w[2 * pg + 1], w[2 * pg + 2]);
#pragma unroll
            for (int m = 0; m < 8; m++)
                g_E[(h * 8 + m) * 8 + c] = yv[m];
        } else if (c >= 64) {
            int s = c - 64;
#pragma unroll
            for (int pg = 0; pg < 32; pg++)
                g_TPi[(h * 32 + pg) * 8 + s] = pack2(w[2 * pg + 1], w[2 * pg + 2]);
#pragma unroll
            for (int m = 0; m < 8; m++)
                g_F[(h * 8 + m) * 8 + s] = yv[m];
        }
    }
}

// ---------------- Kernel 2: 8-step folded scan ----------------
#define NIT (LL / 8)   // 256 iterations

__global__ void __launch_bounds__(32)
scan_kernel(const float* __restrict__ u, float* __restrict__ y) {
    __shared__ ull stg[2][32][4];   // [parity][lane][pair] state staging

    int lane = threadIdx.x & 31;
    int g = lane >> 3;   // sequence within warp (0..3)
    int r = lane & 7;    // lane within group (0..7): owns slots 8r+1..8r+8
    int gl = lane & ~7;  // group leader lane index
    int seq = blockIdx.x * 4 + g;     // 0..8191
    int h = seq & (HH - 1);
    const float4* ub = (const float4*)(u + (size_t)seq * LL);  // 512 float4
    float* yb = y + (size_t)seq * LL;

    // ---- load folded taps (64 ull) + y-solve row (16 floats) ----
    ull GamP[4][8], PiP[4][8];
#pragma unroll
    for (int p = 0; p < 4; p++) {
        int base = (h * 32 + (4 * r + p)) * 8;
#pragma unroll
        for (int j = 0; j < 8; j++) {
            GamP[p][j] = g_TG[base + j];
            PiP[p][j]  = g_TPi[base + j];
        }
    }
    float Ey[8], Fy[8];
#pragma unroll
    for (int j = 0; j < 8; j++) {
        Ey[j] = g_E[(h * 8 + r) * 8 + j];
        Fy[j] = g_F[(h * 8 + r) * 8 + j];
    }

    // prime staging with zero state (both parities for safety)
#pragma unroll
    for (int p = 0; p < 4; p++) { stg[0][lane][p] = 0ull; stg[1][lane][p] = 0ull; }
    __syncthreads();

    // u prefetch: iter n uses ub[2n], ub[2n+1]
    float4 f0 = ub[0], f1 = ub[1], f2 = ub[2], f3 = ub[3];

    auto process = [&](int n, int par, float4 fa, float4 fb) {
        // staged state at iteration start (published by last iter's bar)
        ull nb0 = 0ull, nb1 = 0ull, nb2 = 0ull, nb3 = 0ull;
        if (r < 7) {
            nb0 = stg[par][lane + 1][0];
            nb1 = stg[par][lane + 1][1];
            nb2 = stg[par][lane + 1][2];
            nb3 = stg[par][lane + 1][3];
        }
        ull sa = stg[par][gl][0], sb = stg[par][gl][1];
        ull sc = stg[par][gl][2], sd = stg[par][gl][3];
        float s1, s2, s3, s4, s5, s6, s7, s8;
        unpack2(sa, s1, s2); unpack2(sb, s3, s4);
        unpack2(sc, s5, s6); unpack2(sd, s7, s8);

        // ---- output y_{8n+r} (side work, off every carried chain) ----
        float yr = Ey[0] * s1;
        yr = fmaf(Ey[1], s2, yr); yr = fmaf(Ey[2], s3, yr);
        yr = fmaf(Ey[3], s4, yr); yr = fmaf(Ey[4], s5, yr);
        yr = fmaf(Ey[5], s6, yr); yr = fmaf(Ey[6], s7, yr);
        yr = fmaf(Ey[7], s8, yr);
        yr = fmaf(Fy[0], fa.x, yr); yr = fmaf(Fy[1], fa.y, yr);
        yr = fmaf(Fy[2], fa.z, yr); yr = fmaf(Fy[3], fa.w, yr);
        yr = fmaf(Fy[4], fb.x, yr); yr = fmaf(Fy[5], fb.y, yr);
        yr = fmaf(Fy[6], fb.z, yr); yr = fmaf(Fy[7], fb.w, yr);
        yb[8 * n + r] = yr;

        // ---- duplicate-packed multiplicands (shared by all 4 pairs) ----
        ull Sd0 = pack2(s1, s1), Sd1 = pack2(s2, s2), Sd2 = pack2(s3, s3),
            Sd3 = pack2(s4, s4), Sd4 = pack2(s5, s5), Sd5 = pack2(s6, s6),
            Sd6 = pack2(s7, s7), Sd7 = pack2(s8, s8);
        ull ud0 = pack2(fa.x, fa.x), ud1 = pack2(fa.y, fa.y),
            ud2 = pack2(fa.z, fa.z), ud3 = pack2(fa.w, fa.w),
            ud4 = pack2(fb.x, fb.x), ud5 = pack2(fb.y, fb.y),
            ud6 = pack2(fb.z, fb.z), ud7 = pack2(fb.w, fb.w);

        // ---- 4 pair updates: 16 independent fma2 each, base = neighbor ----
#pragma unroll
        for (int p = 0; p < 4; p++) {
            ull acc = (p == 0) ? nb0 : (p == 1) ? nb1 : (p == 2) ? nb2 : nb3;
            acc = fma2(GamP[p][0], Sd0, acc);
            acc = fma2(GamP[p][1], Sd1, acc);
            acc = fma2(GamP[p][2], Sd2, acc);
            acc = fma2(GamP[p][3], Sd3, acc);
            acc = fma2(GamP[p][4], Sd4, acc);
            acc = fma2(GamP[p][5], Sd5, acc);
            acc = fma2(GamP[p][6], Sd6, acc);
            acc = fma2(GamP[p][7], Sd7, acc);
            acc = fma2(PiP[p][0], ud0, acc);
            acc = fma2(PiP[p][1], ud1, acc);
            acc = fma2(PiP[p][2], ud2, acc);
            acc = fma2(PiP[p][3], ud3, acc);
            acc = fma2(PiP[p][4], ud4, acc);
            acc = fma2(PiP[p][5], ud5, acc);
            acc = fma2(PiP[p][6], ud6, acc);
            acc = fma2(PiP[p][7], ud7, acc);
            stg[1 - par][lane][p] = acc;       // state for next iteration
        }
        __syncthreads();   // publish new state; nw=1 BAR floor + STS drain
    };

    for (int n0 = 0; n0 < NIT; n0 += 2) {
        process(n0, 0, f0, f1);
        int i0 = 2 * n0 + 4;                       // refill for iter n0+2
        f0 = ub[i0 < 512 ? i0 : 511];
        f1 = ub[i0 + 1 < 512 ? i0 + 1 : 511];
        process(n0 + 1, 1, f2, f3);
        int i2 = 2 * n0 + 6;                       // refill for iter n0+3
        f2 = ub[i2 < 512 ? i2 : 511];
        f3 = ub[i2 + 1 < 512 ? i2 + 1 : 511];
    }
}

extern "C" void kernel_launch(void* const* d_in, const int* in_sizes, int n_in,
                              void* d_out, int out_size) {
    const float* u = (const float*)d_in[0];
    const float* k = (const float*)d_in[1];
    if (n_in >= 2 && in_sizes[0] == HH * NN) {  // defensive: swap if order differs
        u = (const float*)d_in[1];
        k = (const float*)d_in[0];
    }
    float* y = (float*)d_out;

    coef_kernel<<<HH, NN>>>(k);
    fold_kernel<<<HH, 96>>>();
    // 8192 sequences, 4 per warp, one warp per CTA -> 2048 CTAs
    scan_kernel<<<(BB * HH) / 4, 32>>>(u, y);
}